// round 3
// baseline (speedup 1.0000x reference)
#include <cuda_runtime.h>
#include <cstdint>
#include <cstddef>

// Problem constants
#define HD 1024
#define ID 2048
#define NSTATE 16
#define RD 64
#define BB 2
#define LL 512
#define ML (BB*LL)

// ---------------------------------------------------------------------------
// Scratch
// ---------------------------------------------------------------------------
__device__ float g_x   [(size_t)ML*ID];
__device__ float g_gate[(size_t)ML*ID];
__device__ float g_u   [(size_t)ML*ID];
__device__ float g_ssm [2][(size_t)ML*96];
__device__ float g_delta[2][(size_t)ML*ID];
__device__ float g_y   [2][(size_t)ML*ID];
__device__ float g_yt  [(size_t)ML*ID];

__device__ __forceinline__ float siluf(float v)     { return v * (1.0f / (1.0f + __expf(-v))); }
__device__ __forceinline__ float softplusf(float v) { return v > 20.f ? v : log1pf(__expf(v)); }

struct GemmArgs {
    const float* A;
    const float* B;
    float*       C;
    const float* bias;
};

// ---------------------------------------------------------------------------
// tf32 split: x ~= hi + lo, both representable in tf32
// ---------------------------------------------------------------------------
__device__ __forceinline__ void tf32_split(float x, uint32_t& h, uint32_t& l) {
    asm("cvt.rna.tf32.f32 %0, %1;" : "=r"(h) : "f"(x));
    float lo = x - __uint_as_float(h);
    asm("cvt.rna.tf32.f32 %0, %1;" : "=r"(l) : "f"(lo));
}

__device__ __forceinline__ void mma16n8k8(float* c, const uint32_t* a, const uint32_t* b) {
    asm volatile(
        "mma.sync.aligned.m16n8k8.row.col.f32.tf32.tf32.f32 "
        "{%0,%1,%2,%3}, {%4,%5,%6,%7}, {%8,%9}, {%0,%1,%2,%3};"
        : "+f"(c[0]), "+f"(c[1]), "+f"(c[2]), "+f"(c[3])
        : "r"(a[0]), "r"(a[1]), "r"(a[2]), "r"(a[3]), "r"(b[0]), "r"(b[1]));
}

// ---------------------------------------------------------------------------
// Tensor-pipe tf32 GEMM via mma.sync (sm_80-baseline PTX; works on sm_100)
// C[M,N] = A[M,K] @ B[N,K]^T, 128x128 tiles, BK=32, 3-pass tf32 split.
// SMEM holds fragment-ordered planes:
//   [0,16K)  A-hi   [16K,32K) A-lo   [32K,48K) B-hi   [48K,64K) B-lo
// A plane: [8 mtile][4 kstep][32 lane] x float4 (one thread's 4 A regs)
// B plane: [16 ntile][4 kstep][32 lane] x float2 (one thread's 2 B regs)
// EPI: 0 = plain store, 1 = softplus(acc + bias[col])
// ---------------------------------------------------------------------------
#define TM_SMEM_BYTES 65536

template<int EPI>
__global__ __launch_bounds__(256, 1)
void tmma(GemmArgs g0, GemmArgs g1, int lda, int ldb, int ldc, int K)
{
    extern __shared__ char smem[];
    float* sAh = reinterpret_cast<float*>(smem);
    float* sAl = sAh + 4096;
    float* sBh = sAl + 4096;
    float* sBl = sBh + 4096;

    GemmArgs g = (blockIdx.z == 0) ? g0 : g1;
    const int tid    = threadIdx.x;
    const int lane   = tid & 31;
    const int wid    = tid >> 5;
    const int warp_m = wid & 1;       // 2 warps over M (64 rows each)
    const int warp_n = wid >> 1;      // 4 warps over N (32 cols each)
    const int row0   = blockIdx.y * 128;
    const int col0   = blockIdx.x * 128;

    float acc[4][4][4];
#pragma unroll
    for (int mt = 0; mt < 4; mt++)
#pragma unroll
        for (int nt = 0; nt < 4; nt++)
#pragma unroll
            for (int j = 0; j < 4; j++) acc[mt][nt][j] = 0.f;

    const int nchunks = K >> 5;
    for (int c = 0; c < nchunks; c++) {
        const int k0 = c << 5;
        __syncthreads();
        // ---- stage: load + split + scatter to fragment order ----
#pragma unroll
        for (int it = 0; it < 4; it++) {
            const int q  = tid + it * 256;     // 0..1023
            const int r  = q >> 3;             // row (m or n), 0..127
            const int cq = q & 7;              // float4 index in 32-wide k
            // A
            {
                float4 v = *reinterpret_cast<const float4*>(
                    g.A + (size_t)(row0 + r) * lda + k0 + cq * 4);
                const float vv[4] = {v.x, v.y, v.z, v.w};
                const int mt = r >> 4, rr = r & 15;
#pragma unroll
                for (int j = 0; j < 4; j++) {
                    const int k = cq * 4 + j;
                    const int ks = k >> 3, kk = k & 7;
                    const int tq = ((rr & 7) << 2) | (kk & 3);
                    const int fs = (rr >> 3) | ((kk >> 2) << 1);
                    const int d  = ((((mt << 2) | ks) << 5 | tq) << 2) | fs;
                    uint32_t h, l;
                    tf32_split(vv[j], h, l);
                    sAh[d] = __uint_as_float(h);
                    sAl[d] = __uint_as_float(l);
                }
            }
            // B
            {
                float4 v = *reinterpret_cast<const float4*>(
                    g.B + (size_t)(col0 + r) * ldb + k0 + cq * 4);
                const float vv[4] = {v.x, v.y, v.z, v.w};
                const int nt = r >> 3, rr = r & 7;
#pragma unroll
                for (int j = 0; j < 4; j++) {
                    const int k = cq * 4 + j;
                    const int ks = k >> 3, kk = k & 7;
                    const int tq = (rr << 2) | (kk & 3);
                    const int fs = kk >> 2;
                    const int d  = ((((nt << 2) | ks) << 5 | tq) << 1) | fs;
                    uint32_t h, l;
                    tf32_split(vv[j], h, l);
                    sBh[d] = __uint_as_float(h);
                    sBl[d] = __uint_as_float(l);
                }
            }
        }
        __syncthreads();

        // ---- compute: 3 passes (Ah*Bh, Ah*Bl, Al*Bh) ----
        const float* pa[3] = {sAh, sAh, sAl};
        const float* pb[3] = {sBh, sBl, sBh};
#pragma unroll
        for (int p = 0; p < 3; p++) {
            const float* Aplane = pa[p];
            const float* Bplane = pb[p];
#pragma unroll
            for (int ks = 0; ks < 4; ks++) {
                uint32_t af[4][4];
                uint32_t bf[4][2];
#pragma unroll
                for (int mt = 0; mt < 4; mt++) {
                    const int wm = warp_m * 4 + mt;
                    const uint4 v = *reinterpret_cast<const uint4*>(
                        Aplane + ((((wm << 2) | ks) << 5 | lane) << 2));
                    af[mt][0] = v.x; af[mt][1] = v.y; af[mt][2] = v.z; af[mt][3] = v.w;
                }
#pragma unroll
                for (int nt = 0; nt < 4; nt++) {
                    const int wn = warp_n * 4 + nt;
                    const uint2 v = *reinterpret_cast<const uint2*>(
                        Bplane + ((((wn << 2) | ks) << 5 | lane) << 1));
                    bf[nt][0] = v.x; bf[nt][1] = v.y;
                }
#pragma unroll
                for (int mt = 0; mt < 4; mt++)
#pragma unroll
                    for (int nt = 0; nt < 4; nt++)
                        mma16n8k8(acc[mt][nt], af[mt], bf[nt]);
            }
        }
    }

    // ---- epilogue ----
    const int rw = lane >> 2;
    const int cw = (lane & 3) * 2;
#pragma unroll
    for (int mt = 0; mt < 4; mt++) {
        const int m = row0 + warp_m * 64 + mt * 16 + rw;
#pragma unroll
        for (int nt = 0; nt < 4; nt++) {
            const int n = col0 + warp_n * 32 + nt * 8 + cw;
            float v0 = acc[mt][nt][0], v1 = acc[mt][nt][1];
            float v2 = acc[mt][nt][2], v3 = acc[mt][nt][3];
            if (EPI == 1) {
                const float b0 = __ldg(g.bias + n);
                const float b1 = __ldg(g.bias + n + 1);
                v0 = softplusf(v0 + b0); v1 = softplusf(v1 + b1);
                v2 = softplusf(v2 + b0); v3 = softplusf(v3 + b1);
            }
            *reinterpret_cast<float2*>(g.C + (size_t)m * ldc + n)       = make_float2(v0, v1);
            *reinterpret_cast<float2*>(g.C + (size_t)(m + 8) * ldc + n) = make_float2(v2, v3);
        }
    }
}

// ---------------------------------------------------------------------------
// SIMT SGEMM (kept for G3: N=96)
// ---------------------------------------------------------------------------
template<int BM, int BN, int BK, int TM, int TN, int EPI>
__global__ __launch_bounds__((BM/TM)*(BN/TN))
void sgemm(GemmArgs g0, GemmArgs g1, int lda, int ldb, int ldc, int K)
{
    constexpr int THREADS = (BM/TM)*(BN/TN);
    constexpr int KV = BK/4;
    __shared__ float As[BK][BM];
    __shared__ float Bs[BK][BN];
    GemmArgs g = (blockIdx.z == 0) ? g0 : g1;
    const int tid  = threadIdx.x;
    const int row0 = blockIdx.y * BM;
    const int col0 = blockIdx.x * BN;
    const float* __restrict__ Ap = g.A + (size_t)row0 * lda;
    const float* __restrict__ Bp = g.B + (size_t)col0 * ldb;
    float acc[TM][TN];
#pragma unroll
    for (int i = 0; i < TM; i++)
#pragma unroll
        for (int j = 0; j < TN; j++) acc[i][j] = 0.f;
    const int tcol = tid % (BN/TN);
    const int trow = tid / (BN/TN);
    for (int k0 = 0; k0 < K; k0 += BK) {
#pragma unroll
        for (int idx = tid; idx < BM*KV; idx += THREADS) {
            int rr = idx / KV, kv = idx % KV;
            float4 v = *reinterpret_cast<const float4*>(Ap + (size_t)rr*lda + k0 + kv*4);
            As[kv*4+0][rr] = v.x; As[kv*4+1][rr] = v.y;
            As[kv*4+2][rr] = v.z; As[kv*4+3][rr] = v.w;
        }
#pragma unroll
        for (int idx = tid; idx < BN*KV; idx += THREADS) {
            int rr = idx / KV, kv = idx % KV;
            float4 v = *reinterpret_cast<const float4*>(Bp + (size_t)rr*ldb + k0 + kv*4);
            Bs[kv*4+0][rr] = v.x; Bs[kv*4+1][rr] = v.y;
            Bs[kv*4+2][rr] = v.z; Bs[kv*4+3][rr] = v.w;
        }
        __syncthreads();
#pragma unroll
        for (int k = 0; k < BK; k++) {
            float a[TM], b[TN];
#pragma unroll
            for (int i = 0; i < TM; i += 4) {
                float4 v = *reinterpret_cast<const float4*>(&As[k][trow*TM + i]);
                a[i] = v.x; a[i+1] = v.y; a[i+2] = v.z; a[i+3] = v.w;
            }
            if constexpr (TN == 2) {
                float2 v = *reinterpret_cast<const float2*>(&Bs[k][tcol*TN]);
                b[0] = v.x; b[1] = v.y;
            } else {
#pragma unroll
                for (int j = 0; j < TN; j += 4) {
                    float4 v = *reinterpret_cast<const float4*>(&Bs[k][tcol*TN + j]);
                    b[j] = v.x; b[j+1] = v.y; b[j+2] = v.z; b[j+3] = v.w;
                }
            }
#pragma unroll
            for (int i = 0; i < TM; i++)
#pragma unroll
                for (int j = 0; j < TN; j++)
                    acc[i][j] = fmaf(a[i], b[j], acc[i][j]);
        }
        __syncthreads();
    }
#pragma unroll
    for (int i = 0; i < TM; i++) {
        int rr = row0 + trow*TM + i;
#pragma unroll
        for (int j = 0; j < TN; j++) {
            int cc = col0 + tcol*TN + j;
            float v = acc[i][j];
            if (EPI == 1) v = softplusf(v + g.bias[cc]);
            g.C[(size_t)rr*ldc + cc] = v;
        }
    }
}

// ---------------------------------------------------------------------------
// conv + silu
// ---------------------------------------------------------------------------
__global__ void conv_silu_kernel(const float* __restrict__ w,
                                 const float* __restrict__ bias)
{
    int idx = blockIdx.x * blockDim.x + threadIdx.x;
    int i = idx % ID;
    int l = (idx / ID) % LL;
    float acc = bias[i];
#pragma unroll
    for (int k = 0; k < 4; k++) {
        int ls = l - 3 + k;
        if (ls >= 0) acc = fmaf(g_x[(size_t)idx + (ptrdiff_t)(k-3)*ID], w[i*4 + k], acc);
    }
    g_u[idx] = siluf(acc);
}

// ---------------------------------------------------------------------------
// selective scan
// ---------------------------------------------------------------------------
__global__ void scan_kernel(const float* __restrict__ Alog_f,
                            const float* __restrict__ Alog_b,
                            const float* __restrict__ D_f,
                            const float* __restrict__ D_b)
{
    int gw   = (blockIdx.x * blockDim.x + threadIdx.x) >> 5;
    int lane = threadIdx.x & 31;
    int dir  = gw >> 11;
    int b    = (gw >> 10) & 1;
    int i    = ((gw & 1023) << 1) | (lane >> 4);
    int n    = lane & 15;

    const float* Alog = dir ? Alog_b : Alog_f;
    float An = -expf(Alog[i*NSTATE + n]);
    float Dv = dir ? D_b[i] : D_f[i];

    const float* dbase = g_delta[dir] + (size_t)(b*LL)*ID + i;
    const float* ubase = g_u          + (size_t)(b*LL)*ID + i;
    const float* sbase = g_ssm[dir]   + (size_t)(b*LL)*96;
    float*       ybase = g_y[dir]     + (size_t)(b*LL)*ID + i;

    int l0 = dir ? (LL-1) : 0;
    ptrdiff_t dstep = dir ? -(ptrdiff_t)ID : (ptrdiff_t)ID;
    ptrdiff_t sstep = dir ? -96 : 96;

    const float* dp = dbase + (size_t)l0*ID;
    const float* up = ubase + (size_t)l0*ID;
    const float* sp = sbase + (size_t)l0*96;
    float*       yp = ybase + (size_t)l0*ID;

    float x = 0.f;
    for (int t = 0; t < LL; t++) {
        float d  = __ldg(dp);
        float uu = __ldg(up);
        float Bv = __ldg(sp + RD + n);
        float Cv = __ldg(sp + RD + NSTATE + n);
        float dA = __expf(d * An);
        x = fmaf(x, dA, d * Bv * uu);
        float p = x * Cv;
        p += __shfl_xor_sync(0xffffffffu, p, 1);
        p += __shfl_xor_sync(0xffffffffu, p, 2);
        p += __shfl_xor_sync(0xffffffffu, p, 4);
        p += __shfl_xor_sync(0xffffffffu, p, 8);
        if (n == 0) *yp = fmaf(uu, Dv, p);
        dp += dstep; up += dstep; sp += sstep; yp += dstep;
    }
}

__global__ void combine_kernel()
{
    int idx = blockIdx.x * blockDim.x + threadIdx.x;
    g_yt[idx] = (g_y[0][idx] + g_y[1][idx]) * siluf(g_gate[idx]);
}

// ---------------------------------------------------------------------------
// Launch
// ---------------------------------------------------------------------------
extern "C" void kernel_launch(void* const* d_in, const int* in_sizes, int n_in,
                              void* d_out, int out_size)
{
    const float* hs     = (const float*)d_in[0];
    const float* hs2    = (const float*)d_in[1];
    const float* in_w   = (const float*)d_in[2];
    const float* in_dw  = (const float*)d_in[3];
    const float* conv_w = (const float*)d_in[4];
    const float* conv_b = (const float*)d_in[5];
    const float* xw_f   = (const float*)d_in[6];
    const float* xw_b   = (const float*)d_in[7];
    const float* dtw_f  = (const float*)d_in[8];
    const float* dtb_f  = (const float*)d_in[9];
    const float* dtw_b  = (const float*)d_in[10];
    const float* dtb_b  = (const float*)d_in[11];
    const float* Alog_f = (const float*)d_in[12];
    const float* Alog_b = (const float*)d_in[13];
    const float* D_f    = (const float*)d_in[14];
    const float* D_b    = (const float*)d_in[15];
    const float* outw   = (const float*)d_in[16];
    float* out = (float*)d_out;

    float *px, *pgate, *pu, *pssm, *pdelta, *pyt;
    cudaGetSymbolAddress((void**)&px,     g_x);
    cudaGetSymbolAddress((void**)&pgate,  g_gate);
    cudaGetSymbolAddress((void**)&pu,     g_u);
    cudaGetSymbolAddress((void**)&pssm,   g_ssm);
    cudaGetSymbolAddress((void**)&pdelta, g_delta);
    cudaGetSymbolAddress((void**)&pyt,    g_yt);
    float* pssm0 = pssm;
    float* pssm1 = pssm + (size_t)ML*96;
    float* pd0   = pdelta;
    float* pd1   = pdelta + (size_t)ML*ID;

    cudaFuncSetAttribute(tmma<0>, cudaFuncAttributeMaxDynamicSharedMemorySize, TM_SMEM_BYTES);
    cudaFuncSetAttribute(tmma<1>, cudaFuncAttributeMaxDynamicSharedMemorySize, TM_SMEM_BYTES);

    // G1: x = hs @ in_w[:I]^T ; gate = hs2 @ in_dw[I:2I]^T  (tensor)
    {
        GemmArgs a{hs,  in_w,                    px,    nullptr};
        GemmArgs b{hs2, in_dw + (size_t)ID * HD, pgate, nullptr};
        dim3 grid(ID/128, ML/128, 2);
        tmma<0><<<grid, 256, TM_SMEM_BYTES>>>(a, b, HD, HD, ID, HD);
    }

    conv_silu_kernel<<<(ML*ID)/256, 256>>>(conv_w, conv_b);

    // G3: ssm[dir] = u @ x_proj(_back)_w^T   (SIMT, N=96)
    {
        GemmArgs a{pu, xw_f, pssm0, nullptr};
        GemmArgs b{pu, xw_b, pssm1, nullptr};
        dim3 grid(96/32, ML/64, 2);
        sgemm<64,32,16,4,2,0><<<grid, 256>>>(a, b, ID, ID, 96, ID);
    }

    // G4: delta = softplus(ssm[:, :64] @ dt_w^T + b)   (tensor)
    {
        GemmArgs a{pssm0, dtw_f, pd0, dtb_f};
        GemmArgs b{pssm1, dtw_b, pd1, dtb_b};
        dim3 grid(ID/128, ML/128, 2);
        tmma<1><<<grid, 256, TM_SMEM_BYTES>>>(a, b, 96, RD, ID, RD);
    }

    scan_kernel<<<512, 256>>>(Alog_f, Alog_b, D_f, D_b);
    combine_kernel<<<(ML*ID)/256, 256>>>();

    // G5: out = yt @ out_proj_w^T   (tensor)
    {
        GemmArgs a{pyt, outw, out, nullptr};
        dim3 grid(HD/128, ML/128, 1);
        tmma<0><<<grid, 256, TM_SMEM_BYTES>>>(a, a, ID, ID, HD, ID);
    }

    (void)in_sizes; (void)n_in; (void)out_size;
}

// round 4
// speedup vs baseline: 1.8864x; 1.8864x over previous
#include <cuda_runtime.h>
#include <cuda_fp16.h>
#include <cstdint>
#include <cstddef>

// Problem constants
#define HD 1024
#define ID 2048
#define NSTATE 16
#define RD 64
#define BB 2
#define LL 512
#define ML (BB*LL)

// ---------------------------------------------------------------------------
// Scratch
// ---------------------------------------------------------------------------
__device__ __align__(16) float g_x   [(size_t)ML*ID];
__device__ __align__(16) float g_gate[(size_t)ML*ID];
__device__ __align__(16) float g_u   [(size_t)ML*ID];
__device__ __align__(16) float g_ssm [2][(size_t)ML*96];
__device__ __align__(16) float g_delta[2][(size_t)ML*ID];
__device__ __align__(16) float g_y   [2][(size_t)ML*ID];
__device__ __align__(16) float g_yt  [(size_t)ML*ID];

// fp16 split-plane pools (fragment-packed u32 = half2 pairs)
// layout per matrix: [rowblock][chunk][2048 u32]
#define U_HS_A    0u
#define U_HS2_A   524288u
#define U_INW_B   1048576u
#define U_INDW_B  2097152u
#define U_SSM0_A  3145728u
#define U_SSM1_A  3178496u
#define U_DTW0_B  3211264u
#define U_DTW1_B  3276800u
#define U_YT_A    3342336u
#define U_OUTW_B  4390912u
#define U_TOTAL   5439488u
__device__ __align__(16) unsigned g_hi[U_TOTAL];
__device__ __align__(16) unsigned g_lo[U_TOTAL];

__device__ __forceinline__ float siluf(float v)     { return v * (1.0f / (1.0f + __expf(-v))); }
__device__ __forceinline__ float softplusf(float v) { return v > 20.f ? v : log1pf(__expf(v)); }

// ---------------------------------------------------------------------------
// Converters: fp32 matrix -> fragment-packed fp16 hi/lo planes in gmem.
// One block handles one 128x32 chunk. Coalesced read via smem, coalesced write.
// ---------------------------------------------------------------------------
__device__ __forceinline__ void split_pack(float x0, float x1, unsigned& ph, unsigned& pl) {
    __half h0 = __float2half_rn(x0), h1 = __float2half_rn(x1);
    __half l0 = __float2half_rn(x0 - __half2float(h0));
    __half l1 = __float2half_rn(x1 - __half2float(h1));
    ph = ((unsigned)__half_as_ushort(h1) << 16) | __half_as_ushort(h0);
    pl = ((unsigned)__half_as_ushort(l1) << 16) | __half_as_ushort(l0);
}

// A layout (m16n8k16 A fragment): within 128x32 chunk:
//   mt=r>>4, ks=k>>4, rr=r&15, kk=k&15
//   lane=((rr&7)<<2)|((kk>>1)&3), reg=(rr>>3)|((kk>>3)<<1), half=kk&1
//   u32 idx = (((mt*2+ks)*32)+lane)*4 + reg
__global__ __launch_bounds__(256) void convA(const float* __restrict__ src, int ld, int nchunks,
                                             unsigned off)
{
    __shared__ float s[128][33];
    const int tid = threadIdx.x;
    const int rb = blockIdx.y, c = blockIdx.x;
    const float* sp = src + (size_t)(rb*128)*ld + c*32;
#pragma unroll
    for (int it = 0; it < 4; it++) {
        int r = (tid>>3) + it*32, c4 = tid&7;
        float4 v = *reinterpret_cast<const float4*>(sp + (size_t)r*ld + c4*4);
        s[r][c4*4+0]=v.x; s[r][c4*4+1]=v.y; s[r][c4*4+2]=v.z; s[r][c4*4+3]=v.w;
    }
    __syncthreads();
    unsigned* oh = g_hi + off + (size_t)(rb*nchunks + c)*2048;
    unsigned* ol = g_lo + off + (size_t)(rb*nchunks + c)*2048;
#pragma unroll
    for (int j = 0; j < 8; j++) {
        int idx = tid + 256*j;
        int reg = idx&3, lane=(idx>>2)&31, ks=(idx>>7)&1, mt=idx>>8;
        int r = mt*16 + ((reg&1)<<3) + (lane>>2);
        int k = ks*16 + ((reg>>1)<<3) + ((lane&3)<<1);
        unsigned ph, pl;
        split_pack(s[r][k], s[r][k+1], ph, pl);
        oh[idx] = ph; ol[idx] = pl;
    }
}

// B layout (m16n8k16 B fragment, N x K source): within 128x32 chunk:
//   nt=n>>3, ks=k>>4, rr=n&7, kk=k&15
//   lane=(rr<<2)|((kk&7)>>1), reg=kk>>3, half=kk&1
//   u32 idx = ((nt*2+ks)*32+lane)*2 + reg
__global__ __launch_bounds__(256) void convB(const float* __restrict__ src, int ld, int nchunks,
                                             unsigned off)
{
    __shared__ float s[128][33];
    const int tid = threadIdx.x;
    const int rb = blockIdx.y, c = blockIdx.x;
    const float* sp = src + (size_t)(rb*128)*ld + c*32;
#pragma unroll
    for (int it = 0; it < 4; it++) {
        int r = (tid>>3) + it*32, c4 = tid&7;
        float4 v = *reinterpret_cast<const float4*>(sp + (size_t)r*ld + c4*4);
        s[r][c4*4+0]=v.x; s[r][c4*4+1]=v.y; s[r][c4*4+2]=v.z; s[r][c4*4+3]=v.w;
    }
    __syncthreads();
    unsigned* oh = g_hi + off + (size_t)(rb*nchunks + c)*2048;
    unsigned* ol = g_lo + off + (size_t)(rb*nchunks + c)*2048;
#pragma unroll
    for (int j = 0; j < 8; j++) {
        int idx = tid + 256*j;
        int reg = idx&1, lane=(idx>>1)&31, ks=(idx>>6)&1, nt=idx>>7;
        int n = nt*8 + (lane>>2);
        int k = ks*16 + reg*8 + ((lane&3)<<1);
        unsigned ph, pl;
        split_pack(s[n][k], s[n][k+1], ph, pl);
        oh[idx] = ph; ol[idx] = pl;
    }
}

// ---------------------------------------------------------------------------
// fp16 3-pass split GEMM: C = A @ B^T, 128x128 tiles, BK=32, cp.async double buffer.
// ---------------------------------------------------------------------------
struct HArgs { unsigned aoff; unsigned boff; float* C; const float* bias; };

__device__ __forceinline__ void mma_h(float* c, const unsigned* a, const unsigned* b) {
    asm volatile(
        "mma.sync.aligned.m16n8k16.row.col.f32.f16.f16.f32 "
        "{%0,%1,%2,%3},{%4,%5,%6,%7},{%8,%9},{%0,%1,%2,%3};"
        : "+f"(c[0]), "+f"(c[1]), "+f"(c[2]), "+f"(c[3])
        : "r"(a[0]), "r"(a[1]), "r"(a[2]), "r"(a[3]), "r"(b[0]), "r"(b[1]));
}
__device__ __forceinline__ void cp16(unsigned saddr, const void* g) {
    asm volatile("cp.async.cg.shared.global [%0], [%1], 16;" :: "r"(saddr), "l"(g));
}

#define HG_SMEM_BYTES 65536   // 2 stages x 32KB (Ah 8K | Al 8K | Bh 8K | Bl 8K)

template<int EPI>
__global__ __launch_bounds__(256) void hgemm(HArgs h0, HArgs h1, int nchunks, int ldc)
{
    extern __shared__ unsigned sm[];
    const unsigned sbase = (unsigned)__cvta_generic_to_shared(sm);
    HArgs h = blockIdx.z ? h1 : h0;
    const int tid = threadIdx.x, lane = tid & 31, wid = tid >> 5;
    const int warp_m = wid & 1, warp_n = wid >> 1;
    const unsigned* gAh = g_hi + h.aoff + (size_t)blockIdx.y * nchunks * 2048;
    const unsigned* gAl = g_lo + h.aoff + (size_t)blockIdx.y * nchunks * 2048;
    const unsigned* gBh = g_hi + h.boff + (size_t)blockIdx.x * nchunks * 2048;
    const unsigned* gBl = g_lo + h.boff + (size_t)blockIdx.x * nchunks * 2048;

    auto issue = [&](int s, int c) {
        const unsigned dst = sbase + s * 32768;
        const unsigned* srcs[4] = {gAh + c*2048, gAl + c*2048, gBh + c*2048, gBl + c*2048};
#pragma unroll
        for (int p = 0; p < 4; p++)
#pragma unroll
            for (int q = 0; q < 2; q++) {
                const int o = (tid + q*256) * 4;   // u32 index, 16B granular
                cp16(dst + p*8192 + o*4, srcs[p] + o);
            }
        asm volatile("cp.async.commit_group;");
    };

    float acc[4][4][4];
#pragma unroll
    for (int mt = 0; mt < 4; mt++)
#pragma unroll
        for (int nt = 0; nt < 4; nt++)
#pragma unroll
            for (int j = 0; j < 4; j++) acc[mt][nt][j] = 0.f;

    issue(0, 0);
    for (int c = 0; c < nchunks; c++) {
        if (c + 1 < nchunks) {
            issue((c + 1) & 1, c + 1);
            asm volatile("cp.async.wait_group 1;");
        } else {
            asm volatile("cp.async.wait_group 0;");
        }
        __syncthreads();
        const unsigned* st  = sm + (c & 1) * 8192;
        const unsigned* sAh = st;
        const unsigned* sAl = st + 2048;
        const unsigned* sBh = st + 4096;
        const unsigned* sBl = st + 6144;
#pragma unroll
        for (int ks = 0; ks < 2; ks++) {
            unsigned ah[4][4], al[4][4], bh[4][2], bl[4][2];
#pragma unroll
            for (int mt = 0; mt < 4; mt++) {
                const int base = (((warp_m*4 + mt)*2 + ks)*32 + lane) * 4;
                uint4 v = *reinterpret_cast<const uint4*>(sAh + base);
                ah[mt][0]=v.x; ah[mt][1]=v.y; ah[mt][2]=v.z; ah[mt][3]=v.w;
                v = *reinterpret_cast<const uint4*>(sAl + base);
                al[mt][0]=v.x; al[mt][1]=v.y; al[mt][2]=v.z; al[mt][3]=v.w;
            }
#pragma unroll
            for (int nt = 0; nt < 4; nt++) {
                const int base = (((warp_n*4 + nt)*2 + ks)*32 + lane) * 2;
                uint2 v = *reinterpret_cast<const uint2*>(sBh + base);
                bh[nt][0]=v.x; bh[nt][1]=v.y;
                v = *reinterpret_cast<const uint2*>(sBl + base);
                bl[nt][0]=v.x; bl[nt][1]=v.y;
            }
#pragma unroll
            for (int mt = 0; mt < 4; mt++)
#pragma unroll
                for (int nt = 0; nt < 4; nt++) mma_h(acc[mt][nt], ah[mt], bh[nt]);
#pragma unroll
            for (int mt = 0; mt < 4; mt++)
#pragma unroll
                for (int nt = 0; nt < 4; nt++) mma_h(acc[mt][nt], ah[mt], bl[nt]);
#pragma unroll
            for (int mt = 0; mt < 4; mt++)
#pragma unroll
                for (int nt = 0; nt < 4; nt++) mma_h(acc[mt][nt], al[mt], bh[nt]);
        }
        __syncthreads();
    }

    // epilogue
    const int row0 = blockIdx.y * 128, col0 = blockIdx.x * 128;
    const int rw = lane >> 2;
    const int cw = (lane & 3) * 2;
#pragma unroll
    for (int mt = 0; mt < 4; mt++) {
        const int m = row0 + warp_m*64 + mt*16 + rw;
#pragma unroll
        for (int nt = 0; nt < 4; nt++) {
            const int n = col0 + warp_n*32 + nt*8 + cw;
            float v0 = acc[mt][nt][0], v1 = acc[mt][nt][1];
            float v2 = acc[mt][nt][2], v3 = acc[mt][nt][3];
            if (EPI == 1) {
                const float b0 = __ldg(h.bias + n);
                const float b1 = __ldg(h.bias + n + 1);
                v0 = softplusf(v0 + b0); v1 = softplusf(v1 + b1);
                v2 = softplusf(v2 + b0); v3 = softplusf(v3 + b1);
            }
            *reinterpret_cast<float2*>(h.C + (size_t)m * ldc + n)       = make_float2(v0, v1);
            *reinterpret_cast<float2*>(h.C + (size_t)(m + 8) * ldc + n) = make_float2(v2, v3);
        }
    }
}

// ---------------------------------------------------------------------------
// SIMT SGEMM (G3: N=96)
// ---------------------------------------------------------------------------
struct GemmArgs { const float* A; const float* B; float* C; const float* bias; };

template<int BM, int BN, int BK, int TM, int TN>
__global__ __launch_bounds__((BM/TM)*(BN/TN))
void sgemm(GemmArgs g0, GemmArgs g1, int lda, int ldb, int ldc, int K)
{
    constexpr int THREADS = (BM/TM)*(BN/TN);
    constexpr int KV = BK/4;
    __shared__ float As[BK][BM];
    __shared__ float Bs[BK][BN];
    GemmArgs g = (blockIdx.z == 0) ? g0 : g1;
    const int tid  = threadIdx.x;
    const int row0 = blockIdx.y * BM;
    const int col0 = blockIdx.x * BN;
    const float* __restrict__ Ap = g.A + (size_t)row0 * lda;
    const float* __restrict__ Bp = g.B + (size_t)col0 * ldb;
    float acc[TM][TN];
#pragma unroll
    for (int i = 0; i < TM; i++)
#pragma unroll
        for (int j = 0; j < TN; j++) acc[i][j] = 0.f;
    const int tcol = tid % (BN/TN);
    const int trow = tid / (BN/TN);
    for (int k0 = 0; k0 < K; k0 += BK) {
#pragma unroll
        for (int idx = tid; idx < BM*KV; idx += THREADS) {
            int rr = idx / KV, kv = idx % KV;
            float4 v = *reinterpret_cast<const float4*>(Ap + (size_t)rr*lda + k0 + kv*4);
            As[kv*4+0][rr] = v.x; As[kv*4+1][rr] = v.y;
            As[kv*4+2][rr] = v.z; As[kv*4+3][rr] = v.w;
        }
#pragma unroll
        for (int idx = tid; idx < BN*KV; idx += THREADS) {
            int rr = idx / KV, kv = idx % KV;
            float4 v = *reinterpret_cast<const float4*>(Bp + (size_t)rr*ldb + k0 + kv*4);
            Bs[kv*4+0][rr] = v.x; Bs[kv*4+1][rr] = v.y;
            Bs[kv*4+2][rr] = v.z; Bs[kv*4+3][rr] = v.w;
        }
        __syncthreads();
#pragma unroll
        for (int k = 0; k < BK; k++) {
            float a[TM], b[TN];
#pragma unroll
            for (int i = 0; i < TM; i += 4) {
                float4 v = *reinterpret_cast<const float4*>(&As[k][trow*TM + i]);
                a[i] = v.x; a[i+1] = v.y; a[i+2] = v.z; a[i+3] = v.w;
            }
            if constexpr (TN == 2) {
                float2 v = *reinterpret_cast<const float2*>(&Bs[k][tcol*TN]);
                b[0] = v.x; b[1] = v.y;
            } else {
#pragma unroll
                for (int j = 0; j < TN; j += 4) {
                    float4 v = *reinterpret_cast<const float4*>(&Bs[k][tcol*TN + j]);
                    b[j] = v.x; b[j+1] = v.y; b[j+2] = v.z; b[j+3] = v.w;
                }
            }
#pragma unroll
            for (int i = 0; i < TM; i++)
#pragma unroll
                for (int j = 0; j < TN; j++)
                    acc[i][j] = fmaf(a[i], b[j], acc[i][j]);
        }
        __syncthreads();
    }
#pragma unroll
    for (int i = 0; i < TM; i++) {
        int rr = row0 + trow*TM + i;
#pragma unroll
        for (int j = 0; j < TN; j++) {
            int cc = col0 + tcol*TN + j;
            g.C[(size_t)rr*ldc + cc] = acc[i][j];
        }
    }
}

// ---------------------------------------------------------------------------
// conv + silu
// ---------------------------------------------------------------------------
__global__ void conv_silu_kernel(const float* __restrict__ w,
                                 const float* __restrict__ bias)
{
    int idx = blockIdx.x * blockDim.x + threadIdx.x;
    int i = idx % ID;
    int l = (idx / ID) % LL;
    float acc = bias[i];
#pragma unroll
    for (int k = 0; k < 4; k++) {
        int ls = l - 3 + k;
        if (ls >= 0) acc = fmaf(g_x[(size_t)idx + (ptrdiff_t)(k-3)*ID], w[i*4 + k], acc);
    }
    g_u[idx] = siluf(acc);
}

// ---------------------------------------------------------------------------
// selective scan
// ---------------------------------------------------------------------------
__global__ void scan_kernel(const float* __restrict__ Alog_f,
                            const float* __restrict__ Alog_b,
                            const float* __restrict__ D_f,
                            const float* __restrict__ D_b)
{
    int gw   = (blockIdx.x * blockDim.x + threadIdx.x) >> 5;
    int lane = threadIdx.x & 31;
    int dir  = gw >> 11;
    int b    = (gw >> 10) & 1;
    int i    = ((gw & 1023) << 1) | (lane >> 4);
    int n    = lane & 15;

    const float* Alog = dir ? Alog_b : Alog_f;
    float An = -expf(Alog[i*NSTATE + n]);
    float Dv = dir ? D_b[i] : D_f[i];

    const float* dbase = g_delta[dir] + (size_t)(b*LL)*ID + i;
    const float* ubase = g_u          + (size_t)(b*LL)*ID + i;
    const float* sbase = g_ssm[dir]   + (size_t)(b*LL)*96;
    float*       ybase = g_y[dir]     + (size_t)(b*LL)*ID + i;

    int l0 = dir ? (LL-1) : 0;
    ptrdiff_t dstep = dir ? -(ptrdiff_t)ID : (ptrdiff_t)ID;
    ptrdiff_t sstep = dir ? -96 : 96;

    const float* dp = dbase + (size_t)l0*ID;
    const float* up = ubase + (size_t)l0*ID;
    const float* sp = sbase + (size_t)l0*96;
    float*       yp = ybase + (size_t)l0*ID;

    float x = 0.f;
    for (int t = 0; t < LL; t++) {
        float d  = __ldg(dp);
        float uu = __ldg(up);
        float Bv = __ldg(sp + RD + n);
        float Cv = __ldg(sp + RD + NSTATE + n);
        float dA = __expf(d * An);
        x = fmaf(x, dA, d * Bv * uu);
        float p = x * Cv;
        p += __shfl_xor_sync(0xffffffffu, p, 1);
        p += __shfl_xor_sync(0xffffffffu, p, 2);
        p += __shfl_xor_sync(0xffffffffu, p, 4);
        p += __shfl_xor_sync(0xffffffffu, p, 8);
        if (n == 0) *yp = fmaf(uu, Dv, p);
        dp += dstep; up += dstep; sp += sstep; yp += dstep;
    }
}

__global__ void combine_kernel()
{
    int idx = blockIdx.x * blockDim.x + threadIdx.x;
    g_yt[idx] = (g_y[0][idx] + g_y[1][idx]) * siluf(g_gate[idx]);
}

// ---------------------------------------------------------------------------
// Launch
// ---------------------------------------------------------------------------
extern "C" void kernel_launch(void* const* d_in, const int* in_sizes, int n_in,
                              void* d_out, int out_size)
{
    const float* hs     = (const float*)d_in[0];
    const float* hs2    = (const float*)d_in[1];
    const float* in_w   = (const float*)d_in[2];
    const float* in_dw  = (const float*)d_in[3];
    const float* conv_w = (const float*)d_in[4];
    const float* conv_b = (const float*)d_in[5];
    const float* xw_f   = (const float*)d_in[6];
    const float* xw_b   = (const float*)d_in[7];
    const float* dtw_f  = (const float*)d_in[8];
    const float* dtb_f  = (const float*)d_in[9];
    const float* dtw_b  = (const float*)d_in[10];
    const float* dtb_b  = (const float*)d_in[11];
    const float* Alog_f = (const float*)d_in[12];
    const float* Alog_b = (const float*)d_in[13];
    const float* D_f    = (const float*)d_in[14];
    const float* D_b    = (const float*)d_in[15];
    const float* outw   = (const float*)d_in[16];
    float* out = (float*)d_out;

    float *px, *pgate, *pu, *pssm, *pdelta, *pyt;
    cudaGetSymbolAddress((void**)&px,     g_x);
    cudaGetSymbolAddress((void**)&pgate,  g_gate);
    cudaGetSymbolAddress((void**)&pu,     g_u);
    cudaGetSymbolAddress((void**)&pssm,   g_ssm);
    cudaGetSymbolAddress((void**)&pdelta, g_delta);
    cudaGetSymbolAddress((void**)&pyt,    g_yt);
    float* pssm0 = pssm;
    float* pssm1 = pssm + (size_t)ML*96;
    float* pd0   = pdelta;
    float* pd1   = pdelta + (size_t)ML*ID;

    cudaFuncSetAttribute(hgemm<0>, cudaFuncAttributeMaxDynamicSharedMemorySize, HG_SMEM_BYTES);
    cudaFuncSetAttribute(hgemm<1>, cudaFuncAttributeMaxDynamicSharedMemorySize, HG_SMEM_BYTES);

    // --- weight + input conversions (independent) ---
    convB<<<dim3(32,16), 256>>>(in_w,                    HD,   32, U_INW_B);
    convB<<<dim3(32,16), 256>>>(in_dw + (size_t)ID*HD,   HD,   32, U_INDW_B);
    convB<<<dim3(2,16),  256>>>(dtw_f,                   RD,   2,  U_DTW0_B);
    convB<<<dim3(2,16),  256>>>(dtw_b,                   RD,   2,  U_DTW1_B);
    convB<<<dim3(64,8),  256>>>(outw,                    ID,   64, U_OUTW_B);
    convA<<<dim3(32,8),  256>>>(hs,                      HD,   32, U_HS_A);
    convA<<<dim3(32,8),  256>>>(hs2,                     HD,   32, U_HS2_A);

    // G1: x = hs @ in_w[:I]^T ; gate = hs2 @ in_dw[I:2I]^T
    {
        HArgs a{U_HS_A,  U_INW_B,  px,    nullptr};
        HArgs b{U_HS2_A, U_INDW_B, pgate, nullptr};
        hgemm<0><<<dim3(ID/128, ML/128, 2), 256, HG_SMEM_BYTES>>>(a, b, 32, ID);
    }

    conv_silu_kernel<<<(ML*ID)/256, 256>>>(conv_w, conv_b);

    // G3: ssm[dir] = u @ x_proj(_back)_w^T   (SIMT, N=96)
    {
        GemmArgs a{pu, xw_f, pssm0, nullptr};
        GemmArgs b{pu, xw_b, pssm1, nullptr};
        sgemm<64,32,16,4,2><<<dim3(96/32, ML/64, 2), 256>>>(a, b, ID, ID, 96, ID);
    }

    // convert ssm dt-slices (cols 0..63, ld=96)
    convA<<<dim3(2,8), 256>>>(pssm0, 96, 2, U_SSM0_A);
    convA<<<dim3(2,8), 256>>>(pssm1, 96, 2, U_SSM1_A);

    // G4: delta = softplus(dt @ dt_w^T + b)
    {
        HArgs a{U_SSM0_A, U_DTW0_B, pd0, dtb_f};
        HArgs b{U_SSM1_A, U_DTW1_B, pd1, dtb_b};
        hgemm<1><<<dim3(ID/128, ML/128, 2), 256, HG_SMEM_BYTES>>>(a, b, 2, ID);
    }

    scan_kernel<<<512, 256>>>(Alog_f, Alog_b, D_f, D_b);
    combine_kernel<<<(ML*ID)/256, 256>>>();

    convA<<<dim3(64,8), 256>>>(pyt, ID, 64, U_YT_A);

    // G5: out = yt @ out_proj_w^T
    {
        HArgs a{U_YT_A, U_OUTW_B, out, nullptr};
        hgemm<0><<<dim3(HD/128, ML/128, 1), 256, HG_SMEM_BYTES>>>(a, a, 64, HD);
    }

    (void)in_sizes; (void)n_in; (void)out_size;
}